// round 13
// baseline (speedup 1.0000x reference)
#include <cuda_runtime.h>
#include <cuda_fp16.h>
#include <stdint.h>

#define NEDGE 262144
#define NTRI  393216
#define TILE_M 64
#define NTH   256
#define NBLK_E (NEDGE/TILE_M)   // 4096
#define NBLK_T (NTRI/TILE_M)    // 6144

// ---- smem byte offsets (per CTA, ~42KB -> 2 CTAs/SM) ----
#define ACT16   0            // 32768 (64 rows x 512B fp16)
#define X0_OFF  0            // 2 slots x 8192 inside ACT16 (dead after L0)
#define L3RED   32768        // 64*12 floats = 3072
#define MISC    36864
#define OFF_W3  (MISC)        // 768 floats
#define OFF_B3  (MISC+3072)
#define OFF_MU  (MISC+3088)   // 100 floats
#define OFF_IDX (MISC+3504)   // 3*64 ints
#define OFF_RN  (MISC+4272)   // 2*64 floats
#define OFF_CS  (MISC+4784)
#define OFF_SS  (MISC+5040)
#define SMEM_TOTAL (MISC+5376)   // 42240

// W fragment images: per 32-k unit: 2 ks x 16 npair x 32 lanes x uint4.
// PTX m16n8k16 B layout (k=2*(l%4)+i, n=l/4 per 8x8 block).
// edges: L0 12 units, L1 8, L2 8 (28). trip: 20+8+8 (36). Units contiguous.
__device__ __align__(16) uint4 g_wfrag_e[28672];  // 28*1024
__device__ __align__(16) uint4 g_wfrag_t[36864];  // 36*1024

__device__ __forceinline__ uint32_t smem_u32(const void* p){
  uint32_t a;
  asm("{ .reg .u64 t; cvta.to.shared.u64 t, %1; cvt.u32.u64 %0, t; }" : "=r"(a) : "l"(p));
  return a;
}
__device__ __forceinline__ void ldsm4(uint32_t (&r)[4], uint32_t a){
  asm volatile("ldmatrix.sync.aligned.m8n8.x4.shared.b16 {%0,%1,%2,%3}, [%4];"
    : "=r"(r[0]), "=r"(r[1]), "=r"(r[2]), "=r"(r[3]) : "r"(a));
}
__device__ __forceinline__ void mma_fp(float (&d)[4], const uint32_t (&a)[4], uint32_t b0, uint32_t b1){
  asm volatile("mma.sync.aligned.m16n8k16.row.col.f32.f16.f16.f32 "
    "{%0,%1,%2,%3}, {%4,%5,%6,%7}, {%8,%9}, {%0,%1,%2,%3};"
    : "+f"(d[0]), "+f"(d[1]), "+f"(d[2]), "+f"(d[3])
    : "r"(a[0]), "r"(a[1]), "r"(a[2]), "r"(a[3]), "r"(b0), "r"(b1));
}
__device__ __forceinline__ uint32_t pack_h2(float x, float y){
  __half2 t = __floats2half2_rn(x, y);
  return *(uint32_t*)&t;
}
__device__ __forceinline__ float silu_f(float x){
  return __fdividef(x, 1.0f + __expf(-x));
}

// ---- prep: write W as PTX B-fragments, one uint4 per (unit,ks,npair,lane) ----
__global__ void prep_frag(const float* __restrict__ eW0, const float* __restrict__ eW1,
                          const float* __restrict__ eW2, const float* __restrict__ tW0,
                          const float* __restrict__ tW1, const float* __restrict__ tW2){
  const int job = blockIdx.y;
  const float* W; uint4* img; int KIN, NU;
  switch (job){
    case 0: W = eW0; img = g_wfrag_e;         KIN = 356; NU = 12; break;
    case 1: W = eW1; img = g_wfrag_e + 12288; KIN = 256; NU = 8;  break;
    case 2: W = eW2; img = g_wfrag_e + 20480; KIN = 256; NU = 8;  break;
    case 3: W = tW0; img = g_wfrag_t;         KIN = 586; NU = 20; break;
    case 4: W = tW1; img = g_wfrag_t + 20480; KIN = 256; NU = 8;  break;
    default:W = tW2; img = g_wfrag_t + 28672; KIN = 256; NU = 8;  break;
  }
  int gid = blockIdx.x * blockDim.x + threadIdx.x;
  if (gid >= NU * 1024) return;
  const int u  = gid >> 10;
  const int ks = (gid >> 9) & 1;
  const int p  = (gid >> 5) & 15;
  const int l  = gid & 31;
  const int kw = u * 32 + ks * 16 + (l & 3) * 2;
  const int na = p * 16 + (l >> 2);
  const int nb = na + 8;
  auto get = [&](int k, int n) -> float { return (k < KIN) ? W[k * 256 + n] : 0.0f; };
  uint4 v;
  v.x = pack_h2(get(kw,     na), get(kw + 1, na));
  v.y = pack_h2(get(kw + 8, na), get(kw + 9, na));
  v.z = pack_h2(get(kw,     nb), get(kw + 1, nb));
  v.w = pack_h2(get(kw + 8, nb), get(kw + 9, nb));
  img[gid] = v;
}

// ---------------- fused MLP body ----------------
// NU0 = # of 32-k units for layer0 (edges 12, trip 20); total units NU0+16.
template<bool TRIP, int KGATH, int NU0>
__device__ __forceinline__ void mlp_body(int bid,
        const float* __restrict__ h,
        const int* __restrict__ i0, const int* __restrict__ i1, const int* __restrict__ i2,
        const float* __restrict__ rn0g, const float* __restrict__ rn1g,
        const float* __restrict__ cvg, const float* __restrict__ svg,
        const float* __restrict__ mug,
        const float* __restrict__ w3g, const float* __restrict__ b3g,
        const uint4* __restrict__ wfrag,
        float* __restrict__ out, unsigned char* sm, uint32_t sb)
{
  const int tid = threadIdx.x, lane = tid & 31, wid = tid >> 5;
  const int wm = wid & 1, wn = wid >> 1;     // 2m x 4n grid, warp tile 32x64
  const int row0 = bid * TILE_M;
  const int NUTOT = NU0 + 16;

  float* w3s = (float*)(sm + OFF_W3);
  float* b3s = (float*)(sm + OFF_B3);
  float* mus = (float*)(sm + OFF_MU);
  int*   idxs = (int*)(sm + OFF_IDX);
  float* rns = (float*)(sm + OFF_RN);
  float* css = (float*)(sm + OFF_CS);
  float* sss = (float*)(sm + OFF_SS);

  if (tid < 64){
    idxs[tid]      = i0[row0 + tid];
    idxs[64 + tid] = i1[row0 + tid];
    rns[tid]       = rn0g[row0 + tid];
    if (TRIP){
      idxs[128 + tid] = i2[row0 + tid];
      rns[64 + tid]   = rn1g[row0 + tid];
      css[tid]        = cvg[row0 + tid];
      sss[tid]        = svg[row0 + tid];
    }
  } else if (tid >= 64 && tid < 164){
    mus[tid - 64] = mug[tid - 64];
  }
  for (int i = tid; i < 768; i += NTH) w3s[i] = w3g[i];
  if (tid < 3) b3s[tid] = b3g[tid];
  __syncthreads();   // idxs/rns/mus visible before genchunk(0)

  float acc[2][8][4];   // [m-block][n8][frag]

  auto feat = [&](int k, int r) -> float {
    if (!TRIP){
      int b = k - 256;
      if ((unsigned)b < 100u){ float d = mus[b] - rns[r]; return __expf(-10.0f * d * d); }
      return 0.0f;
    } else {
      if (k < 484){
        int b = k - 384;
        if (b >= 0 && b < 100){ float d = mus[b] - rns[r]; return __expf(-10.0f * d * d); }
        return 0.0f;
      } else if (k < 584){
        float d = mus[k - 484] - rns[64 + r];
        return __expf(-10.0f * d * d);
      } else if (k == 584) return css[r];
      else if (k == 585)   return sss[r];
      return 0.0f;
    }
  };

  // layer-0 chunk c: 64 rows x 64 k-cols fp16 (4 threads/row, 16 cols each)
  auto genchunk = [&](int c, int slot){
    const int r = tid >> 2, q = tid & 3;
    const int k0 = c * 64 + q * 16;
    unsigned char* hb = sm + X0_OFF + slot * 8192;
    float4 f[4];
    if (c * 64 < KGATH){
      const float4* src = (const float4*)(h + (size_t)idxs[(c >> 1) * 64 + r] * 128 + (k0 & 127));
      f[0] = src[0]; f[1] = src[1]; f[2] = src[2]; f[3] = src[3];
    } else {
      #pragma unroll
      for (int g = 0; g < 4; g++){
        int kk = k0 + g * 4;
        f[g].x = feat(kk, r);   f[g].y = feat(kk+1, r);
        f[g].z = feat(kk+2, r); f[g].w = feat(kk+3, r);
      }
    }
    #pragma unroll
    for (int hf = 0; hf < 2; hf++){
      uint4 v;
      v.x = pack_h2(f[2*hf].x,   f[2*hf].y);
      v.y = pack_h2(f[2*hf].z,   f[2*hf].w);
      v.z = pack_h2(f[2*hf+1].x, f[2*hf+1].y);
      v.w = pack_h2(f[2*hf+1].z, f[2*hf+1].w);
      const unsigned u = (unsigned)(q * 2 + hf);
      const uint32_t off = (uint32_t)(r * 128 + ((u ^ (unsigned)(r & 7)) << 4));
      *(uint4*)(hb + off) = v;
    }
  };

  // load one unit's B frags for this warp (8 LDG.128 from L2-resident image)
  auto loadB = [&](int u, uint4 (&bf)[2][4]){
    #pragma unroll
    for (int ks = 0; ks < 2; ks++)
      #pragma unroll
      for (int jj = 0; jj < 4; jj++)
        bf[ks][jj] = __ldg(&wfrag[(((u*2 + ks)*16) + wn*4 + jj)*32 + lane]);
  };

  // one 32-k unit: warp tile 32x64, A from smem, B from regs
  auto mma_unit = [&](uint32_t aB, int aRB, int kub, const uint4 (&bf)[2][4]){
    #pragma unroll
    for (int ks = 0; ks < 2; ks++){
      const int ku = kub + ks*2 + (lane >> 4);
      const uint32_t sw = (uint32_t)((ku ^ (lane & 7)) << 4);
      uint32_t afr[2][4];
      #pragma unroll
      for (int mb = 0; mb < 2; mb++)
        ldsm4(afr[mb], aB + (uint32_t)((wm*32 + mb*16 + (lane & 15)) * aRB) + sw);
      #pragma unroll
      for (int jj = 0; jj < 4; jj++){
        const uint4 b = bf[ks][jj];
        #pragma unroll
        for (int mb = 0; mb < 2; mb++){
          mma_fp(acc[mb][jj*2 + 0], afr[mb], b.x, b.y);
          mma_fp(acc[mb][jj*2 + 1], afr[mb], b.z, b.w);
        }
      }
    }
  };

  auto zero_acc = [&](){
    #pragma unroll
    for (int t = 0; t < 2; t++)
      #pragma unroll
      for (int j = 0; j < 8; j++)
        #pragma unroll
        for (int q = 0; q < 4; q++) acc[t][j][q] = 0.0f;
  };

  // epilogue: silu(acc) -> fp16 ACT (512B rows, swizzled)
  auto epi_act = [&](){
    #pragma unroll
    for (int mb = 0; mb < 2; mb++){
      #pragma unroll
      for (int j = 0; j < 8; j++){
        const int r  = wm*32 + mb*16 + (lane >> 2);
        const int cc = wn*64 + j*8 + (lane & 3) * 2;
        float s0 = silu_f(acc[mb][j][0]);
        float s1 = silu_f(acc[mb][j][1]);
        float s2 = silu_f(acc[mb][j][2]);
        float s3 = silu_f(acc[mb][j][3]);
        const uint32_t coff = (uint32_t)(((((unsigned)(cc >> 3)) ^ (unsigned)(r & 7)) << 4) + (cc & 7) * 2);
        *(uint32_t*)(sm + ACT16 + r * 512 + coff) = pack_h2(s0, s1);
        const int r2 = r + 8;
        const uint32_t coff2 = (uint32_t)(((((unsigned)(cc >> 3)) ^ (unsigned)(r2 & 7)) << 4) + (cc & 7) * 2);
        *(uint32_t*)(sm + ACT16 + r2 * 512 + coff2) = pack_h2(s2, s3);
      }
    }
  };

  uint4 bufA[2][4], bufB[2][4];
  auto clampu = [&](int u){ return u < NUTOT ? u : NUTOT - 1; };

  // ---- layer 0: double-buffered generated A chunks, B prefetched 1 unit ahead ----
  genchunk(0, 0);
  loadB(0, bufA);
  zero_acc();
  const int NC0 = NU0 / 2;
  for (int c = 0; c < NC0; c++){
    __syncthreads();                       // chunk c visible; slot (c+1)&1 free
    if (c + 1 < NC0) genchunk(c + 1, (c + 1) & 1);
    const uint32_t xb = sb + X0_OFF + (uint32_t)((c & 1) * 8192);
    loadB(2*c + 1, bufB);
    mma_unit(xb, 128, 0, bufA);
    loadB(clampu(2*c + 2), bufA);
    mma_unit(xb, 128, 4, bufB);
  }
  __syncthreads();                          // X0 reads done before ACT overwrite
  epi_act();
  __syncthreads();
  // ---- layer 1: barrier-free, bufA holds unit NU0 ----
  zero_acc();
  for (int p = 0; p < 8; p++){
    const int u = NU0 + p;
    if (!(p & 1)){
      loadB(clampu(u + 1), bufB);
      mma_unit(sb + ACT16, 512, p * 4, bufA);
    } else {
      loadB(clampu(u + 1), bufA);
      mma_unit(sb + ACT16, 512, p * 4, bufB);
    }
  }
  __syncthreads();                          // ACT reads done before overwrite
  epi_act();
  __syncthreads();
  // ---- layer 2: barrier-free, bufA holds unit NU0+8 ----
  zero_acc();
  for (int p = 0; p < 8; p++){
    const int u = NU0 + 8 + p;
    if (!(p & 1)){
      loadB(clampu(u + 1), bufB);
      mma_unit(sb + ACT16, 512, p * 4, bufA);
    } else {
      loadB(clampu(u + 1), bufA);
      mma_unit(sb + ACT16, 512, p * 4, bufB);
    }
  }
  // ---- layer 3: silu(acc) @ W3 from registers, shfl + smem reduce ----
  __syncthreads();                          // ACT dead; L3RED region free
  {
    float* red = (float*)(sm + L3RED);      // [row][wn][3]
    #pragma unroll
    for (int mb = 0; mb < 2; mb++){
      #pragma unroll
      for (int half = 0; half < 2; half++){
        float p0 = 0.f, p1 = 0.f, p2 = 0.f;
        #pragma unroll
        for (int j = 0; j < 8; j++){
          #pragma unroll
          for (int b = 0; b < 2; b++){
            const int c = wn*64 + j*8 + (lane & 3) * 2 + b;
            float v = silu_f(acc[mb][j][half*2 + b]);
            p0 = fmaf(v, w3s[c*3 + 0], p0);
            p1 = fmaf(v, w3s[c*3 + 1], p1);
            p2 = fmaf(v, w3s[c*3 + 2], p2);
          }
        }
        p0 += __shfl_xor_sync(0xFFFFFFFFu, p0, 1);
        p0 += __shfl_xor_sync(0xFFFFFFFFu, p0, 2);
        p1 += __shfl_xor_sync(0xFFFFFFFFu, p1, 1);
        p1 += __shfl_xor_sync(0xFFFFFFFFu, p1, 2);
        p2 += __shfl_xor_sync(0xFFFFFFFFu, p2, 1);
        p2 += __shfl_xor_sync(0xFFFFFFFFu, p2, 2);
        if ((lane & 3) == 0){
          const int row = wm*32 + mb*16 + (lane >> 2) + half*8;
          red[row*12 + wn*3 + 0] = p0;
          red[row*12 + wn*3 + 1] = p1;
          red[row*12 + wn*3 + 2] = p2;
        }
      }
    }
    __syncthreads();
    if (tid < 192){
      const int row = tid / 3, o = tid - row*3;
      float s = b3s[o] + red[row*12 + o] + red[row*12 + 3 + o]
              + red[row*12 + 6 + o] + red[row*12 + 9 + o];
      out[(size_t)(row0 + row) * 3 + o] = s;
    }
  }
}

__global__ void __launch_bounds__(NTH, 2)
mlp_all(const float* __restrict__ h,
        const int* __restrict__ src, const int* __restrict__ dst,
        const float* __restrict__ enorm,
        const int* __restrict__ tsrc, const int* __restrict__ tdi, const int* __restrict__ tdj,
        const float* __restrict__ nij, const float* __restrict__ nik,
        const float* __restrict__ cosv, const float* __restrict__ sinv,
        const float* __restrict__ mu,
        const float* __restrict__ eW3, const float* __restrict__ eb3,
        const float* __restrict__ tW3, const float* __restrict__ tb3,
        float* __restrict__ out)
{
  extern __shared__ __align__(1024) unsigned char sm[];
  const uint32_t sb = smem_u32(sm);
  const int bid = blockIdx.x;
  if (bid < NBLK_E){
    mlp_body<false, 256, 12>(bid, h, src, dst, dst, enorm, enorm, enorm, enorm, mu,
                             eW3, eb3, (const uint4*)g_wfrag_e, out, sm, sb);
  } else {
    mlp_body<true, 384, 20>(bid - NBLK_E, h, tsrc, tdi, tdj, nij, nik, cosv, sinv, mu,
                            tW3, tb3, (const uint4*)g_wfrag_t,
                            out + (size_t)NEDGE * 3, sm, sb);
  }
}

extern "C" void kernel_launch(void* const* d_in, const int* in_sizes, int n_in,
                              void* d_out, int out_size){
  const float* h     = (const float*)d_in[0];
  const int*   src   = (const int*)  d_in[1];
  const int*   dst   = (const int*)  d_in[2];
  const float* enorm = (const float*)d_in[3];
  const int*   tsrc  = (const int*)  d_in[4];
  const int*   tdi   = (const int*)  d_in[5];
  const int*   tdj   = (const int*)  d_in[6];
  const float* nij   = (const float*)d_in[7];
  const float* nik   = (const float*)d_in[8];
  const float* cosv  = (const float*)d_in[9];
  const float* sinv  = (const float*)d_in[10];
  const float* mu    = (const float*)d_in[11];
  const float* eW0   = (const float*)d_in[12];
  const float* eW1   = (const float*)d_in[13];
  const float* eW2   = (const float*)d_in[14];
  const float* eW3   = (const float*)d_in[15];
  const float* eb3   = (const float*)d_in[16];
  const float* tW0   = (const float*)d_in[17];
  const float* tW1   = (const float*)d_in[18];
  const float* tW2   = (const float*)d_in[19];
  const float* tW3   = (const float*)d_in[20];
  const float* tb3   = (const float*)d_in[21];
  float* out = (float*)d_out;

  prep_frag<<<dim3(80, 6), 256>>>(eW0, eW1, eW2, tW0, tW1, tW2);

  cudaFuncSetAttribute(mlp_all, cudaFuncAttributeMaxDynamicSharedMemorySize, SMEM_TOTAL);
  mlp_all<<<NBLK_E + NBLK_T, NTH, SMEM_TOTAL>>>(
      h, src, dst, enorm, tsrc, tdi, tdj, nij, nik, cosv, sinv, mu,
      eW3, eb3, tW3, tb3, out);
}

// round 14
// speedup vs baseline: 1.0006x; 1.0006x over previous
#include <cuda_runtime.h>
#include <cuda_fp16.h>
#include <stdint.h>

#define NEDGE 262144
#define NTRI  393216
#define TILE_M 64
#define NTH   256
#define NBLK_E (NEDGE/TILE_M)   // 4096
#define NBLK_T (NTRI/TILE_M)    // 6144

// ---- smem byte offsets (per CTA, ~42KB -> 2 CTAs/SM) ----
#define ACT16   0            // 32768 (64 rows x 512B fp16)
#define X0_OFF  0            // 2 slots x 8192 inside ACT16 (dead after L0)
#define L3RED   32768        // 64*12 floats = 3072
#define MISC    36864
#define OFF_W3  (MISC)        // 768 floats
#define OFF_B3  (MISC+3072)
#define OFF_MU  (MISC+3088)   // 100 floats
#define OFF_IDX (MISC+3504)   // 3*64 ints
#define OFF_RN  (MISC+4272)   // 2*64 floats
#define OFF_CS  (MISC+4784)
#define OFF_SS  (MISC+5040)
#define SMEM_TOTAL (MISC+5376)   // 42240

// W fragment images: per 32-k unit: 2 ks x 16 npair x 32 lanes x uint4.
// PTX m16n8k16 B layout (k=2*(l%4)+i, n=l/4 per 8x8 block).
// edges: L0 12 units, L1 8, L2 8 (28). trip: 20+8+8 (36). Units contiguous.
__device__ __align__(16) uint4 g_wfrag_e[28672];  // 28*1024
__device__ __align__(16) uint4 g_wfrag_t[36864];  // 36*1024

__device__ __forceinline__ uint32_t smem_u32(const void* p){
  uint32_t a;
  asm("{ .reg .u64 t; cvta.to.shared.u64 t, %1; cvt.u32.u64 %0, t; }" : "=r"(a) : "l"(p));
  return a;
}
__device__ __forceinline__ void ldsm4(uint32_t (&r)[4], uint32_t a){
  asm volatile("ldmatrix.sync.aligned.m8n8.x4.shared.b16 {%0,%1,%2,%3}, [%4];"
    : "=r"(r[0]), "=r"(r[1]), "=r"(r[2]), "=r"(r[3]) : "r"(a));
}
__device__ __forceinline__ void mma_fp(float (&d)[4], const uint32_t (&a)[4], uint32_t b0, uint32_t b1){
  asm volatile("mma.sync.aligned.m16n8k16.row.col.f32.f16.f16.f32 "
    "{%0,%1,%2,%3}, {%4,%5,%6,%7}, {%8,%9}, {%0,%1,%2,%3};"
    : "+f"(d[0]), "+f"(d[1]), "+f"(d[2]), "+f"(d[3])
    : "r"(a[0]), "r"(a[1]), "r"(a[2]), "r"(a[3]), "r"(b0), "r"(b1));
}
__device__ __forceinline__ uint32_t pack_h2(float x, float y){
  __half2 t = __floats2half2_rn(x, y);
  return *(uint32_t*)&t;
}
__device__ __forceinline__ float silu_f(float x){
  return __fdividef(x, 1.0f + __expf(-x));
}

// ---- prep: write W as PTX B-fragments, one uint4 per (unit,ks,npair,lane) ----
__global__ void prep_frag(const float* __restrict__ eW0, const float* __restrict__ eW1,
                          const float* __restrict__ eW2, const float* __restrict__ tW0,
                          const float* __restrict__ tW1, const float* __restrict__ tW2){
  const int job = blockIdx.y;
  const float* W; uint4* img; int KIN, NU;
  switch (job){
    case 0: W = eW0; img = g_wfrag_e;         KIN = 356; NU = 12; break;
    case 1: W = eW1; img = g_wfrag_e + 12288; KIN = 256; NU = 8;  break;
    case 2: W = eW2; img = g_wfrag_e + 20480; KIN = 256; NU = 8;  break;
    case 3: W = tW0; img = g_wfrag_t;         KIN = 586; NU = 20; break;
    case 4: W = tW1; img = g_wfrag_t + 20480; KIN = 256; NU = 8;  break;
    default:W = tW2; img = g_wfrag_t + 28672; KIN = 256; NU = 8;  break;
  }
  int gid = blockIdx.x * blockDim.x + threadIdx.x;
  if (gid >= NU * 1024) return;
  const int u  = gid >> 10;
  const int ks = (gid >> 9) & 1;
  const int p  = (gid >> 5) & 15;
  const int l  = gid & 31;
  const int kw = u * 32 + ks * 16 + (l & 3) * 2;
  const int na = p * 16 + (l >> 2);
  const int nb = na + 8;
  auto get = [&](int k, int n) -> float { return (k < KIN) ? W[k * 256 + n] : 0.0f; };
  uint4 v;
  v.x = pack_h2(get(kw,     na), get(kw + 1, na));
  v.y = pack_h2(get(kw + 8, na), get(kw + 9, na));
  v.z = pack_h2(get(kw,     nb), get(kw + 1, nb));
  v.w = pack_h2(get(kw + 8, nb), get(kw + 9, nb));
  img[gid] = v;
}

// ---------------- fused MLP body ----------------
// NU0 = # of 32-k units for layer0 (edges 12, trip 20); total units NU0+16.
template<bool TRIP, int KGATH, int NU0>
__device__ __forceinline__ void mlp_body(int bid,
        const float* __restrict__ h,
        const int* __restrict__ i0, const int* __restrict__ i1, const int* __restrict__ i2,
        const float* __restrict__ rn0g, const float* __restrict__ rn1g,
        const float* __restrict__ cvg, const float* __restrict__ svg,
        const float* __restrict__ mug,
        const float* __restrict__ w3g, const float* __restrict__ b3g,
        const uint4* __restrict__ wfrag,
        float* __restrict__ out, unsigned char* sm, uint32_t sb)
{
  const int tid = threadIdx.x, lane = tid & 31, wid = tid >> 5;
  const int wm = wid & 1, wn = wid >> 1;     // 2m x 4n grid, warp tile 32x64
  const int row0 = bid * TILE_M;
  const int NUTOT = NU0 + 16;

  float* w3s = (float*)(sm + OFF_W3);
  float* b3s = (float*)(sm + OFF_B3);
  float* mus = (float*)(sm + OFF_MU);
  int*   idxs = (int*)(sm + OFF_IDX);
  float* rns = (float*)(sm + OFF_RN);
  float* css = (float*)(sm + OFF_CS);
  float* sss = (float*)(sm + OFF_SS);

  if (tid < 64){
    idxs[tid]      = i0[row0 + tid];
    idxs[64 + tid] = i1[row0 + tid];
    rns[tid]       = rn0g[row0 + tid];
    if (TRIP){
      idxs[128 + tid] = i2[row0 + tid];
      rns[64 + tid]   = rn1g[row0 + tid];
      css[tid]        = cvg[row0 + tid];
      sss[tid]        = svg[row0 + tid];
    }
  } else if (tid >= 64 && tid < 164){
    mus[tid - 64] = mug[tid - 64];
  }
  for (int i = tid; i < 768; i += NTH) w3s[i] = w3g[i];
  if (tid < 3) b3s[tid] = b3g[tid];
  __syncthreads();   // idxs/rns/mus visible before genchunk(0)

  float acc[2][8][4];   // [m-block][n8][frag]

  auto feat = [&](int k, int r) -> float {
    if (!TRIP){
      int b = k - 256;
      if ((unsigned)b < 100u){ float d = mus[b] - rns[r]; return __expf(-10.0f * d * d); }
      return 0.0f;
    } else {
      if (k < 484){
        int b = k - 384;
        if (b >= 0 && b < 100){ float d = mus[b] - rns[r]; return __expf(-10.0f * d * d); }
        return 0.0f;
      } else if (k < 584){
        float d = mus[k - 484] - rns[64 + r];
        return __expf(-10.0f * d * d);
      } else if (k == 584) return css[r];
      else if (k == 585)   return sss[r];
      return 0.0f;
    }
  };

  // layer-0 chunk c: 64 rows x 64 k-cols fp16 (4 threads/row, 16 cols each)
  auto genchunk = [&](int c, int slot){
    const int r = tid >> 2, q = tid & 3;
    const int k0 = c * 64 + q * 16;
    unsigned char* hb = sm + X0_OFF + slot * 8192;
    float4 f[4];
    if (c * 64 < KGATH){
      const float4* src = (const float4*)(h + (size_t)idxs[(c >> 1) * 64 + r] * 128 + (k0 & 127));
      f[0] = src[0]; f[1] = src[1]; f[2] = src[2]; f[3] = src[3];
    } else {
      #pragma unroll
      for (int g = 0; g < 4; g++){
        int kk = k0 + g * 4;
        f[g].x = feat(kk, r);   f[g].y = feat(kk+1, r);
        f[g].z = feat(kk+2, r); f[g].w = feat(kk+3, r);
      }
    }
    #pragma unroll
    for (int hf = 0; hf < 2; hf++){
      uint4 v;
      v.x = pack_h2(f[2*hf].x,   f[2*hf].y);
      v.y = pack_h2(f[2*hf].z,   f[2*hf].w);
      v.z = pack_h2(f[2*hf+1].x, f[2*hf+1].y);
      v.w = pack_h2(f[2*hf+1].z, f[2*hf+1].w);
      const unsigned u = (unsigned)(q * 2 + hf);
      const uint32_t off = (uint32_t)(r * 128 + ((u ^ (unsigned)(r & 7)) << 4));
      *(uint4*)(hb + off) = v;
    }
  };

  // load one unit's B frags for this warp (8 LDG.128 from L2-resident image)
  auto loadB = [&](int u, uint4 (&bf)[2][4]){
    #pragma unroll
    for (int ks = 0; ks < 2; ks++)
      #pragma unroll
      for (int jj = 0; jj < 4; jj++)
        bf[ks][jj] = __ldg(&wfrag[(((u*2 + ks)*16) + wn*4 + jj)*32 + lane]);
  };

  // one 32-k unit: warp tile 32x64, A from smem, B from regs
  auto mma_unit = [&](uint32_t aB, int aRB, int kub, const uint4 (&bf)[2][4]){
    #pragma unroll
    for (int ks = 0; ks < 2; ks++){
      const int ku = kub + ks*2 + (lane >> 4);
      const uint32_t sw = (uint32_t)((ku ^ (lane & 7)) << 4);
      uint32_t afr[2][4];
      #pragma unroll
      for (int mb = 0; mb < 2; mb++)
        ldsm4(afr[mb], aB + (uint32_t)((wm*32 + mb*16 + (lane & 15)) * aRB) + sw);
      #pragma unroll
      for (int jj = 0; jj < 4; jj++){
        const uint4 b = bf[ks][jj];
        #pragma unroll
        for (int mb = 0; mb < 2; mb++){
          mma_fp(acc[mb][jj*2 + 0], afr[mb], b.x, b.y);
          mma_fp(acc[mb][jj*2 + 1], afr[mb], b.z, b.w);
        }
      }
    }
  };

  auto zero_acc = [&](){
    #pragma unroll
    for (int t = 0; t < 2; t++)
      #pragma unroll
      for (int j = 0; j < 8; j++)
        #pragma unroll
        for (int q = 0; q < 4; q++) acc[t][j][q] = 0.0f;
  };

  // epilogue: silu(acc) -> fp16 ACT (512B rows, swizzled)
  auto epi_act = [&](){
    #pragma unroll
    for (int mb = 0; mb < 2; mb++){
      #pragma unroll
      for (int j = 0; j < 8; j++){
        const int r  = wm*32 + mb*16 + (lane >> 2);
        const int cc = wn*64 + j*8 + (lane & 3) * 2;
        float s0 = silu_f(acc[mb][j][0]);
        float s1 = silu_f(acc[mb][j][1]);
        float s2 = silu_f(acc[mb][j][2]);
        float s3 = silu_f(acc[mb][j][3]);
        const uint32_t coff = (uint32_t)(((((unsigned)(cc >> 3)) ^ (unsigned)(r & 7)) << 4) + (cc & 7) * 2);
        *(uint32_t*)(sm + ACT16 + r * 512 + coff) = pack_h2(s0, s1);
        const int r2 = r + 8;
        const uint32_t coff2 = (uint32_t)(((((unsigned)(cc >> 3)) ^ (unsigned)(r2 & 7)) << 4) + (cc & 7) * 2);
        *(uint32_t*)(sm + ACT16 + r2 * 512 + coff2) = pack_h2(s2, s3);
      }
    }
  };

  uint4 bufA[2][4], bufB[2][4];
  auto clampu = [&](int u){ return u < NUTOT ? u : NUTOT - 1; };

  // ---- layer 0: double-buffered generated A chunks, B prefetched 1 unit ahead ----
  genchunk(0, 0);
  loadB(0, bufA);
  zero_acc();
  const int NC0 = NU0 / 2;
  for (int c = 0; c < NC0; c++){
    __syncthreads();                       // chunk c visible; slot (c+1)&1 free
    if (c + 1 < NC0) genchunk(c + 1, (c + 1) & 1);
    const uint32_t xb = sb + X0_OFF + (uint32_t)((c & 1) * 8192);
    loadB(2*c + 1, bufB);
    mma_unit(xb, 128, 0, bufA);
    loadB(clampu(2*c + 2), bufA);
    mma_unit(xb, 128, 4, bufB);
  }
  __syncthreads();                          // X0 reads done before ACT overwrite
  epi_act();
  __syncthreads();
  // ---- layer 1: barrier-free, bufA holds unit NU0 ----
  zero_acc();
  for (int p = 0; p < 8; p++){
    const int u = NU0 + p;
    if (!(p & 1)){
      loadB(clampu(u + 1), bufB);
      mma_unit(sb + ACT16, 512, p * 4, bufA);
    } else {
      loadB(clampu(u + 1), bufA);
      mma_unit(sb + ACT16, 512, p * 4, bufB);
    }
  }
  __syncthreads();                          // ACT reads done before overwrite
  epi_act();
  __syncthreads();
  // ---- layer 2: barrier-free, bufA holds unit NU0+8 ----
  zero_acc();
  for (int p = 0; p < 8; p++){
    const int u = NU0 + 8 + p;
    if (!(p & 1)){
      loadB(clampu(u + 1), bufB);
      mma_unit(sb + ACT16, 512, p * 4, bufA);
    } else {
      loadB(clampu(u + 1), bufA);
      mma_unit(sb + ACT16, 512, p * 4, bufB);
    }
  }
  // ---- layer 3: silu(acc) @ W3 from registers, shfl + smem reduce ----
  __syncthreads();                          // ACT dead; L3RED region free
  {
    float* red = (float*)(sm + L3RED);      // [row][wn][3]
    #pragma unroll
    for (int mb = 0; mb < 2; mb++){
      #pragma unroll
      for (int half = 0; half < 2; half++){
        float p0 = 0.f, p1 = 0.f, p2 = 0.f;
        #pragma unroll
        for (int j = 0; j < 8; j++){
          #pragma unroll
          for (int b = 0; b < 2; b++){
            const int c = wn*64 + j*8 + (lane & 3) * 2 + b;
            float v = silu_f(acc[mb][j][half*2 + b]);
            p0 = fmaf(v, w3s[c*3 + 0], p0);
            p1 = fmaf(v, w3s[c*3 + 1], p1);
            p2 = fmaf(v, w3s[c*3 + 2], p2);
          }
        }
        p0 += __shfl_xor_sync(0xFFFFFFFFu, p0, 1);
        p0 += __shfl_xor_sync(0xFFFFFFFFu, p0, 2);
        p1 += __shfl_xor_sync(0xFFFFFFFFu, p1, 1);
        p1 += __shfl_xor_sync(0xFFFFFFFFu, p1, 2);
        p2 += __shfl_xor_sync(0xFFFFFFFFu, p2, 1);
        p2 += __shfl_xor_sync(0xFFFFFFFFu, p2, 2);
        if ((lane & 3) == 0){
          const int row = wm*32 + mb*16 + (lane >> 2) + half*8;
          red[row*12 + wn*3 + 0] = p0;
          red[row*12 + wn*3 + 1] = p1;
          red[row*12 + wn*3 + 2] = p2;
        }
      }
    }
    __syncthreads();
    if (tid < 192){
      const int row = tid / 3, o = tid - row*3;
      float s = b3s[o] + red[row*12 + o] + red[row*12 + 3 + o]
              + red[row*12 + 6 + o] + red[row*12 + 9 + o];
      out[(size_t)(row0 + row) * 3 + o] = s;
    }
  }
}

__global__ void __launch_bounds__(NTH, 2)
mlp_all(const float* __restrict__ h,
        const int* __restrict__ src, const int* __restrict__ dst,
        const float* __restrict__ enorm,
        const int* __restrict__ tsrc, const int* __restrict__ tdi, const int* __restrict__ tdj,
        const float* __restrict__ nij, const float* __restrict__ nik,
        const float* __restrict__ cosv, const float* __restrict__ sinv,
        const float* __restrict__ mu,
        const float* __restrict__ eW3, const float* __restrict__ eb3,
        const float* __restrict__ tW3, const float* __restrict__ tb3,
        float* __restrict__ out)
{
  extern __shared__ __align__(1024) unsigned char sm[];
  const uint32_t sb = smem_u32(sm);
  const int bid = blockIdx.x;
  if (bid < NBLK_E){
    mlp_body<false, 256, 12>(bid, h, src, dst, dst, enorm, enorm, enorm, enorm, mu,
                             eW3, eb3, (const uint4*)g_wfrag_e, out, sm, sb);
  } else {
    mlp_body<true, 384, 20>(bid - NBLK_E, h, tsrc, tdi, tdj, nij, nik, cosv, sinv, mu,
                            tW3, tb3, (const uint4*)g_wfrag_t,
                            out + (size_t)NEDGE * 3, sm, sb);
  }
}

extern "C" void kernel_launch(void* const* d_in, const int* in_sizes, int n_in,
                              void* d_out, int out_size){
  const float* h     = (const float*)d_in[0];
  const int*   src   = (const int*)  d_in[1];
  const int*   dst   = (const int*)  d_in[2];
  const float* enorm = (const float*)d_in[3];
  const int*   tsrc  = (const int*)  d_in[4];
  const int*   tdi   = (const int*)  d_in[5];
  const int*   tdj   = (const int*)  d_in[6];
  const float* nij   = (const float*)d_in[7];
  const float* nik   = (const float*)d_in[8];
  const float* cosv  = (const float*)d_in[9];
  const float* sinv  = (const float*)d_in[10];
  const float* mu    = (const float*)d_in[11];
  const float* eW0   = (const float*)d_in[12];
  const float* eW1   = (const float*)d_in[13];
  const float* eW2   = (const float*)d_in[14];
  const float* eW3   = (const float*)d_in[15];
  const float* eb3   = (const float*)d_in[16];
  const float* tW0   = (const float*)d_in[17];
  const float* tW1   = (const float*)d_in[18];
  const float* tW2   = (const float*)d_in[19];
  const float* tW3   = (const float*)d_in[20];
  const float* tb3   = (const float*)d_in[21];
  float* out = (float*)d_out;

  prep_frag<<<dim3(80, 6), 256>>>(eW0, eW1, eW2, tW0, tW1, tW2);

  cudaFuncSetAttribute(mlp_all, cudaFuncAttributeMaxDynamicSharedMemorySize, SMEM_TOTAL);
  mlp_all<<<NBLK_E + NBLK_T, NTH, SMEM_TOTAL>>>(
      h, src, dst, enorm, tsrc, tdi, tdj, nij, nik, cosv, sinv, mu,
      eW3, eb3, tW3, tb3, out);
}

// round 15
// speedup vs baseline: 1.0012x; 1.0006x over previous
#include <cuda_runtime.h>
#include <cuda_fp16.h>
#include <stdint.h>

#define NEDGE 262144
#define NTRI  393216
#define TILE_M 64
#define NTH   256
#define NBLK_E (NEDGE/TILE_M)   // 4096
#define NBLK_T (NTRI/TILE_M)    // 6144

// ---- smem byte offsets (per CTA, ~42KB -> 2 CTAs/SM) ----
#define ACT16   0            // 32768 (64 rows x 512B fp16)
#define X0_OFF  0            // 2 slots x 8192 inside ACT16 (dead after L0)
#define L3RED   32768        // 64*12 floats = 3072
#define MISC    36864
#define OFF_W3  (MISC)        // 768 floats
#define OFF_B3  (MISC+3072)
#define OFF_MU  (MISC+3088)   // 100 floats
#define OFF_IDX (MISC+3504)   // 3*64 ints
#define OFF_RN  (MISC+4272)   // 2*64 floats
#define OFF_CS  (MISC+4784)
#define OFF_SS  (MISC+5040)
#define SMEM_TOTAL (MISC+5376)   // 42240

// W fragment images: per 32-k unit: 2 ks x 16 npair x 32 lanes x uint4.
// PTX m16n8k16 B layout (k=2*(l%4)+i, n=l/4 per 8x8 block).
// edges: L0 12 units, L1 8, L2 8 (28). trip: 20+8+8 (36). Units contiguous.
__device__ __align__(16) uint4 g_wfrag_e[28672];  // 28*1024
__device__ __align__(16) uint4 g_wfrag_t[36864];  // 36*1024

__device__ __forceinline__ uint32_t smem_u32(const void* p){
  uint32_t a;
  asm("{ .reg .u64 t; cvta.to.shared.u64 t, %1; cvt.u32.u64 %0, t; }" : "=r"(a) : "l"(p));
  return a;
}
__device__ __forceinline__ void ldsm4(uint32_t (&r)[4], uint32_t a){
  asm volatile("ldmatrix.sync.aligned.m8n8.x4.shared.b16 {%0,%1,%2,%3}, [%4];"
    : "=r"(r[0]), "=r"(r[1]), "=r"(r[2]), "=r"(r[3]) : "r"(a));
}
__device__ __forceinline__ void mma_fp(float (&d)[4], const uint32_t (&a)[4], uint32_t b0, uint32_t b1){
  asm volatile("mma.sync.aligned.m16n8k16.row.col.f32.f16.f16.f32 "
    "{%0,%1,%2,%3}, {%4,%5,%6,%7}, {%8,%9}, {%0,%1,%2,%3};"
    : "+f"(d[0]), "+f"(d[1]), "+f"(d[2]), "+f"(d[3])
    : "r"(a[0]), "r"(a[1]), "r"(a[2]), "r"(a[3]), "r"(b0), "r"(b1));
}
__device__ __forceinline__ uint32_t pack_h2(float x, float y){
  __half2 t = __floats2half2_rn(x, y);
  return *(uint32_t*)&t;
}
__device__ __forceinline__ float silu_f(float x){
  return __fdividef(x, 1.0f + __expf(-x));
}

// ---- prep: write W as PTX B-fragments, one uint4 per (unit,ks,npair,lane) ----
__global__ void prep_frag(const float* __restrict__ eW0, const float* __restrict__ eW1,
                          const float* __restrict__ eW2, const float* __restrict__ tW0,
                          const float* __restrict__ tW1, const float* __restrict__ tW2){
  const int job = blockIdx.y;
  const float* W; uint4* img; int KIN, NU;
  switch (job){
    case 0: W = eW0; img = g_wfrag_e;         KIN = 356; NU = 12; break;
    case 1: W = eW1; img = g_wfrag_e + 12288; KIN = 256; NU = 8;  break;
    case 2: W = eW2; img = g_wfrag_e + 20480; KIN = 256; NU = 8;  break;
    case 3: W = tW0; img = g_wfrag_t;         KIN = 586; NU = 20; break;
    case 4: W = tW1; img = g_wfrag_t + 20480; KIN = 256; NU = 8;  break;
    default:W = tW2; img = g_wfrag_t + 28672; KIN = 256; NU = 8;  break;
  }
  int gid = blockIdx.x * blockDim.x + threadIdx.x;
  if (gid >= NU * 1024) return;
  const int u  = gid >> 10;
  const int ks = (gid >> 9) & 1;
  const int p  = (gid >> 5) & 15;
  const int l  = gid & 31;
  const int kw = u * 32 + ks * 16 + (l & 3) * 2;
  const int na = p * 16 + (l >> 2);
  const int nb = na + 8;
  auto get = [&](int k, int n) -> float { return (k < KIN) ? W[k * 256 + n] : 0.0f; };
  uint4 v;
  v.x = pack_h2(get(kw,     na), get(kw + 1, na));
  v.y = pack_h2(get(kw + 8, na), get(kw + 9, na));
  v.z = pack_h2(get(kw,     nb), get(kw + 1, nb));
  v.w = pack_h2(get(kw + 8, nb), get(kw + 9, nb));
  img[gid] = v;
}

// ---------------- fused MLP body ----------------
// NU0 = # of 32-k units for layer0 (edges 12, trip 20); total units NU0+16.
template<bool TRIP, int KGATH, int NU0>
__device__ __forceinline__ void mlp_body(int bid,
        const float* __restrict__ h,
        const int* __restrict__ i0, const int* __restrict__ i1, const int* __restrict__ i2,
        const float* __restrict__ rn0g, const float* __restrict__ rn1g,
        const float* __restrict__ cvg, const float* __restrict__ svg,
        const float* __restrict__ mug,
        const float* __restrict__ w3g, const float* __restrict__ b3g,
        const uint4* __restrict__ wfrag,
        float* __restrict__ out, unsigned char* sm, uint32_t sb)
{
  const int tid = threadIdx.x, lane = tid & 31, wid = tid >> 5;
  const int wm = wid & 1, wn = wid >> 1;     // 2m x 4n grid, warp tile 32x64
  const int row0 = bid * TILE_M;
  const int NUTOT = NU0 + 16;

  float* w3s = (float*)(sm + OFF_W3);
  float* b3s = (float*)(sm + OFF_B3);
  float* mus = (float*)(sm + OFF_MU);
  int*   idxs = (int*)(sm + OFF_IDX);
  float* rns = (float*)(sm + OFF_RN);
  float* css = (float*)(sm + OFF_CS);
  float* sss = (float*)(sm + OFF_SS);

  if (tid < 64){
    idxs[tid]      = i0[row0 + tid];
    idxs[64 + tid] = i1[row0 + tid];
    rns[tid]       = rn0g[row0 + tid];
    if (TRIP){
      idxs[128 + tid] = i2[row0 + tid];
      rns[64 + tid]   = rn1g[row0 + tid];
      css[tid]        = cvg[row0 + tid];
      sss[tid]        = svg[row0 + tid];
    }
  } else if (tid >= 64 && tid < 164){
    mus[tid - 64] = mug[tid - 64];
  }
  for (int i = tid; i < 768; i += NTH) w3s[i] = w3g[i];
  if (tid < 3) b3s[tid] = b3g[tid];
  __syncthreads();   // idxs/rns/mus visible before genchunk(0)

  float acc[2][8][4];   // [m-block][n8][frag]

  auto feat = [&](int k, int r) -> float {
    if (!TRIP){
      int b = k - 256;
      if ((unsigned)b < 100u){ float d = mus[b] - rns[r]; return __expf(-10.0f * d * d); }
      return 0.0f;
    } else {
      if (k < 484){
        int b = k - 384;
        if (b >= 0 && b < 100){ float d = mus[b] - rns[r]; return __expf(-10.0f * d * d); }
        return 0.0f;
      } else if (k < 584){
        float d = mus[k - 484] - rns[64 + r];
        return __expf(-10.0f * d * d);
      } else if (k == 584) return css[r];
      else if (k == 585)   return sss[r];
      return 0.0f;
    }
  };

  // layer-0 chunk c: 64 rows x 64 k-cols fp16 (4 threads/row, 16 cols each)
  auto genchunk = [&](int c, int slot){
    const int r = tid >> 2, q = tid & 3;
    const int k0 = c * 64 + q * 16;
    unsigned char* hb = sm + X0_OFF + slot * 8192;
    float4 f[4];
    if (c * 64 < KGATH){
      const float4* src = (const float4*)(h + (size_t)idxs[(c >> 1) * 64 + r] * 128 + (k0 & 127));
      f[0] = src[0]; f[1] = src[1]; f[2] = src[2]; f[3] = src[3];
    } else {
      #pragma unroll
      for (int g = 0; g < 4; g++){
        int kk = k0 + g * 4;
        f[g].x = feat(kk, r);   f[g].y = feat(kk+1, r);
        f[g].z = feat(kk+2, r); f[g].w = feat(kk+3, r);
      }
    }
    #pragma unroll
    for (int hf = 0; hf < 2; hf++){
      uint4 v;
      v.x = pack_h2(f[2*hf].x,   f[2*hf].y);
      v.y = pack_h2(f[2*hf].z,   f[2*hf].w);
      v.z = pack_h2(f[2*hf+1].x, f[2*hf+1].y);
      v.w = pack_h2(f[2*hf+1].z, f[2*hf+1].w);
      const unsigned u = (unsigned)(q * 2 + hf);
      const uint32_t off = (uint32_t)(r * 128 + ((u ^ (unsigned)(r & 7)) << 4));
      *(uint4*)(hb + off) = v;
    }
  };

  // load one unit's B frags for this warp (8 LDG.128 from L2-resident image)
  auto loadB = [&](int u, uint4 (&bf)[2][4]){
    #pragma unroll
    for (int ks = 0; ks < 2; ks++)
      #pragma unroll
      for (int jj = 0; jj < 4; jj++)
        bf[ks][jj] = __ldg(&wfrag[(((u*2 + ks)*16) + wn*4 + jj)*32 + lane]);
  };

  // one 32-k unit: warp tile 32x64, A from smem, B from regs
  auto mma_unit = [&](uint32_t aB, int aRB, int kub, const uint4 (&bf)[2][4]){
    #pragma unroll
    for (int ks = 0; ks < 2; ks++){
      const int ku = kub + ks*2 + (lane >> 4);
      const uint32_t sw = (uint32_t)((ku ^ (lane & 7)) << 4);
      uint32_t afr[2][4];
      #pragma unroll
      for (int mb = 0; mb < 2; mb++)
        ldsm4(afr[mb], aB + (uint32_t)((wm*32 + mb*16 + (lane & 15)) * aRB) + sw);
      #pragma unroll
      for (int jj = 0; jj < 4; jj++){
        const uint4 b = bf[ks][jj];
        #pragma unroll
        for (int mb = 0; mb < 2; mb++){
          mma_fp(acc[mb][jj*2 + 0], afr[mb], b.x, b.y);
          mma_fp(acc[mb][jj*2 + 1], afr[mb], b.z, b.w);
        }
      }
    }
  };

  auto zero_acc = [&](){
    #pragma unroll
    for (int t = 0; t < 2; t++)
      #pragma unroll
      for (int j = 0; j < 8; j++)
        #pragma unroll
        for (int q = 0; q < 4; q++) acc[t][j][q] = 0.0f;
  };

  // epilogue: silu(acc) -> fp16 ACT (512B rows, swizzled)
  auto epi_act = [&](){
    #pragma unroll
    for (int mb = 0; mb < 2; mb++){
      #pragma unroll
      for (int j = 0; j < 8; j++){
        const int r  = wm*32 + mb*16 + (lane >> 2);
        const int cc = wn*64 + j*8 + (lane & 3) * 2;
        float s0 = silu_f(acc[mb][j][0]);
        float s1 = silu_f(acc[mb][j][1]);
        float s2 = silu_f(acc[mb][j][2]);
        float s3 = silu_f(acc[mb][j][3]);
        const uint32_t coff = (uint32_t)(((((unsigned)(cc >> 3)) ^ (unsigned)(r & 7)) << 4) + (cc & 7) * 2);
        *(uint32_t*)(sm + ACT16 + r * 512 + coff) = pack_h2(s0, s1);
        const int r2 = r + 8;
        const uint32_t coff2 = (uint32_t)(((((unsigned)(cc >> 3)) ^ (unsigned)(r2 & 7)) << 4) + (cc & 7) * 2);
        *(uint32_t*)(sm + ACT16 + r2 * 512 + coff2) = pack_h2(s2, s3);
      }
    }
  };

  uint4 bufA[2][4], bufB[2][4];
  auto clampu = [&](int u){ return u < NUTOT ? u : NUTOT - 1; };

  // ---- layer 0: double-buffered generated A chunks, B prefetched 1 unit ahead ----
  genchunk(0, 0);
  loadB(0, bufA);
  zero_acc();
  const int NC0 = NU0 / 2;
  for (int c = 0; c < NC0; c++){
    __syncthreads();                       // chunk c visible; slot (c+1)&1 free
    if (c + 1 < NC0) genchunk(c + 1, (c + 1) & 1);
    const uint32_t xb = sb + X0_OFF + (uint32_t)((c & 1) * 8192);
    loadB(2*c + 1, bufB);
    mma_unit(xb, 128, 0, bufA);
    loadB(clampu(2*c + 2), bufA);
    mma_unit(xb, 128, 4, bufB);
  }
  __syncthreads();                          // X0 reads done before ACT overwrite
  epi_act();
  __syncthreads();
  // ---- layer 1: barrier-free, bufA holds unit NU0 ----
  zero_acc();
  for (int p = 0; p < 8; p++){
    const int u = NU0 + p;
    if (!(p & 1)){
      loadB(clampu(u + 1), bufB);
      mma_unit(sb + ACT16, 512, p * 4, bufA);
    } else {
      loadB(clampu(u + 1), bufA);
      mma_unit(sb + ACT16, 512, p * 4, bufB);
    }
  }
  __syncthreads();                          // ACT reads done before overwrite
  epi_act();
  __syncthreads();
  // ---- layer 2: barrier-free, bufA holds unit NU0+8 ----
  zero_acc();
  for (int p = 0; p < 8; p++){
    const int u = NU0 + 8 + p;
    if (!(p & 1)){
      loadB(clampu(u + 1), bufB);
      mma_unit(sb + ACT16, 512, p * 4, bufA);
    } else {
      loadB(clampu(u + 1), bufA);
      mma_unit(sb + ACT16, 512, p * 4, bufB);
    }
  }
  // ---- layer 3: silu(acc) @ W3 from registers, shfl + smem reduce ----
  __syncthreads();                          // ACT dead; L3RED region free
  {
    float* red = (float*)(sm + L3RED);      // [row][wn][3]
    #pragma unroll
    for (int mb = 0; mb < 2; mb++){
      #pragma unroll
      for (int half = 0; half < 2; half++){
        float p0 = 0.f, p1 = 0.f, p2 = 0.f;
        #pragma unroll
        for (int j = 0; j < 8; j++){
          #pragma unroll
          for (int b = 0; b < 2; b++){
            const int c = wn*64 + j*8 + (lane & 3) * 2 + b;
            float v = silu_f(acc[mb][j][half*2 + b]);
            p0 = fmaf(v, w3s[c*3 + 0], p0);
            p1 = fmaf(v, w3s[c*3 + 1], p1);
            p2 = fmaf(v, w3s[c*3 + 2], p2);
          }
        }
        p0 += __shfl_xor_sync(0xFFFFFFFFu, p0, 1);
        p0 += __shfl_xor_sync(0xFFFFFFFFu, p0, 2);
        p1 += __shfl_xor_sync(0xFFFFFFFFu, p1, 1);
        p1 += __shfl_xor_sync(0xFFFFFFFFu, p1, 2);
        p2 += __shfl_xor_sync(0xFFFFFFFFu, p2, 1);
        p2 += __shfl_xor_sync(0xFFFFFFFFu, p2, 2);
        if ((lane & 3) == 0){
          const int row = wm*32 + mb*16 + (lane >> 2) + half*8;
          red[row*12 + wn*3 + 0] = p0;
          red[row*12 + wn*3 + 1] = p1;
          red[row*12 + wn*3 + 2] = p2;
        }
      }
    }
    __syncthreads();
    if (tid < 192){
      const int row = tid / 3, o = tid - row*3;
      float s = b3s[o] + red[row*12 + o] + red[row*12 + 3 + o]
              + red[row*12 + 6 + o] + red[row*12 + 9 + o];
      out[(size_t)(row0 + row) * 3 + o] = s;
    }
  }
}

__global__ void __launch_bounds__(NTH, 2)
mlp_all(const float* __restrict__ h,
        const int* __restrict__ src, const int* __restrict__ dst,
        const float* __restrict__ enorm,
        const int* __restrict__ tsrc, const int* __restrict__ tdi, const int* __restrict__ tdj,
        const float* __restrict__ nij, const float* __restrict__ nik,
        const float* __restrict__ cosv, const float* __restrict__ sinv,
        const float* __restrict__ mu,
        const float* __restrict__ eW3, const float* __restrict__ eb3,
        const float* __restrict__ tW3, const float* __restrict__ tb3,
        float* __restrict__ out)
{
  extern __shared__ __align__(1024) unsigned char sm[];
  const uint32_t sb = smem_u32(sm);
  const int bid = blockIdx.x;
  if (bid < NBLK_E){
    mlp_body<false, 256, 12>(bid, h, src, dst, dst, enorm, enorm, enorm, enorm, mu,
                             eW3, eb3, (const uint4*)g_wfrag_e, out, sm, sb);
  } else {
    mlp_body<true, 384, 20>(bid - NBLK_E, h, tsrc, tdi, tdj, nij, nik, cosv, sinv, mu,
                            tW3, tb3, (const uint4*)g_wfrag_t,
                            out + (size_t)NEDGE * 3, sm, sb);
  }
}

extern "C" void kernel_launch(void* const* d_in, const int* in_sizes, int n_in,
                              void* d_out, int out_size){
  const float* h     = (const float*)d_in[0];
  const int*   src   = (const int*)  d_in[1];
  const int*   dst   = (const int*)  d_in[2];
  const float* enorm = (const float*)d_in[3];
  const int*   tsrc  = (const int*)  d_in[4];
  const int*   tdi   = (const int*)  d_in[5];
  const int*   tdj   = (const int*)  d_in[6];
  const float* nij   = (const float*)d_in[7];
  const float* nik   = (const float*)d_in[8];
  const float* cosv  = (const float*)d_in[9];
  const float* sinv  = (const float*)d_in[10];
  const float* mu    = (const float*)d_in[11];
  const float* eW0   = (const float*)d_in[12];
  const float* eW1   = (const float*)d_in[13];
  const float* eW2   = (const float*)d_in[14];
  const float* eW3   = (const float*)d_in[15];
  const float* eb3   = (const float*)d_in[16];
  const float* tW0   = (const float*)d_in[17];
  const float* tW1   = (const float*)d_in[18];
  const float* tW2   = (const float*)d_in[19];
  const float* tW3   = (const float*)d_in[20];
  const float* tb3   = (const float*)d_in[21];
  float* out = (float*)d_out;

  prep_frag<<<dim3(80, 6), 256>>>(eW0, eW1, eW2, tW0, tW1, tW2);

  cudaFuncSetAttribute(mlp_all, cudaFuncAttributeMaxDynamicSharedMemorySize, SMEM_TOTAL);
  mlp_all<<<NBLK_E + NBLK_T, NTH, SMEM_TOTAL>>>(
      h, src, dst, enorm, tsrc, tdi, tdj, nij, nik, cosv, sinv, mu,
      eW3, eb3, tW3, tb3, out);
}